// round 3
// baseline (speedup 1.0000x reference)
#include <cuda_runtime.h>
#include <cuda_bf16.h>
#include <stdint.h>

#define NN 50000
#define EE 800000
#define C  128

// ---------------- scratch (device globals; no allocation) ----------------
__device__ float g_bufA[(size_t)NN * C];
__device__ float g_bufB[(size_t)NN * C];
__device__ int   g_deg[NN];
__device__ float g_dinv[NN];
__device__ int   g_rowptr[NN + 1];
__device__ int   g_cnt[NN];
__device__ int   g_srcs[EE];

// ---------------- degree / CSR ----------------
__global__ void k_zero_deg() {
    int i = blockIdx.x * blockDim.x + threadIdx.x;
    if (i < NN) g_deg[i] = 0;
}

// edge_index is int32 (JAX demotes int64 without x64 mode): [2, E] row-major.
__global__ void k_count_deg(const int* __restrict__ ei) {
    int e = blockIdx.x * blockDim.x + threadIdx.x;
    if (e < EE) {
        int d = ei[EE + e];
        atomicAdd(&g_deg[d], 1);
    }
}

__global__ void k_dinv() {
    int i = blockIdx.x * blockDim.x + threadIdx.x;
    if (i < NN) g_dinv[i] = rsqrtf((float)g_deg[i] + 1.0f);
}

// single-block exclusive scan of g_deg -> g_rowptr, g_cnt
__global__ void k_scan() {
    __shared__ int sh[1024];
    __shared__ int s_carry;
    int tid = threadIdx.x;
    if (tid == 0) s_carry = 0;
    __syncthreads();
    for (int base = 0; base < NN; base += 1024) {
        int i = base + tid;
        int v = (i < NN) ? g_deg[i] : 0;
        sh[tid] = v;
        __syncthreads();
        #pragma unroll
        for (int off = 1; off < 1024; off <<= 1) {
            int t = 0;
            if (tid >= off) t = sh[tid - off];
            __syncthreads();
            sh[tid] += t;
            __syncthreads();
        }
        int incl = sh[tid];
        int carry = s_carry;
        __syncthreads();
        if (i < NN) {
            int rp = carry + incl - v;
            g_rowptr[i] = rp;
            g_cnt[i]    = rp;
        }
        if (tid == 1023) s_carry = carry + sh[1023];
        __syncthreads();
    }
    if (tid == 0) g_rowptr[NN] = s_carry;
}

__global__ void k_fill_csr(const int* __restrict__ ei) {
    int e = blockIdx.x * blockDim.x + threadIdx.x;
    if (e < EE) {
        int s = ei[e];
        int d = ei[EE + e];
        int pos = atomicAdd(&g_cnt[d], 1);
        g_srcs[pos] = s;
    }
}

// ---------------- GEMM body: out[n,128] = X[n,128] @ W[128,128] ----------
// block = 256 threads (8 warps); 32 rows per block; K tiled in 2 chunks of 64.
// static shared: Ws 64x128 (32 KB) + Xs 32x64 (8 KB) = 40 KB.
__device__ __forceinline__ void gemm128_body(const float* __restrict__ X,
                                             const float* __restrict__ W,
                                             float* __restrict__ out, int n) {
    __shared__ float4 Ws4[64 * 32];  // 64 k-rows x 128 cols
    __shared__ float4 Xs4[32 * 16];  // 32 rows x 64 k-cols

    int tid = threadIdx.x;
    int warp = tid >> 5, lane = tid & 31;
    int row0 = blockIdx.x * 32;
    int r0 = warp * 4;

    float acc[4][4];
    #pragma unroll
    for (int i = 0; i < 4; i++)
        #pragma unroll
        for (int j = 0; j < 4; j++) acc[i][j] = 0.f;

    #pragma unroll
    for (int kc = 0; kc < 2; kc++) {
        const float4* W4 = (const float4*)(W + (size_t)kc * 64 * C);
        #pragma unroll
        for (int i = 0; i < 8; i++) Ws4[tid + 256 * i] = W4[tid + 256 * i];

        #pragma unroll
        for (int i = 0; i < 2; i++) {
            int idx = tid + 256 * i;          // r = idx/16, k4 = idx%16
            int r = idx >> 4, k4 = idx & 15;
            float4 v = make_float4(0.f, 0.f, 0.f, 0.f);
            if (row0 + r < n)
                v = ((const float4*)X)[(size_t)(row0 + r) * 32 + kc * 16 + k4];
            Xs4[idx] = v;
        }
        __syncthreads();

        #pragma unroll 4
        for (int k4 = 0; k4 < 16; k4++) {
            float4 xv[4];
            #pragma unroll
            for (int i = 0; i < 4; i++) xv[i] = Xs4[(r0 + i) * 16 + k4];
            #pragma unroll
            for (int j = 0; j < 4; j++) {
                float4 wv = Ws4[(k4 * 4 + j) * 32 + lane];
                #pragma unroll
                for (int i = 0; i < 4; i++) {
                    float xk = (j == 0) ? xv[i].x : (j == 1) ? xv[i].y
                             : (j == 2) ? xv[i].z : xv[i].w;
                    acc[i][0] = fmaf(xk, wv.x, acc[i][0]);
                    acc[i][1] = fmaf(xk, wv.y, acc[i][1]);
                    acc[i][2] = fmaf(xk, wv.z, acc[i][2]);
                    acc[i][3] = fmaf(xk, wv.w, acc[i][3]);
                }
            }
        }
        __syncthreads();
    }

    #pragma unroll
    for (int i = 0; i < 4; i++) {
        int r = row0 + r0 + i;
        if (r < n)
            ((float4*)out)[(size_t)r * 32 + lane] =
                make_float4(acc[i][0], acc[i][1], acc[i][2], acc[i][3]);
    }
}

// ---------------- aggregation body ----------------
__device__ __forceinline__ void agg_body(const float* __restrict__ h,
                                         const float* __restrict__ bias,
                                         float* __restrict__ out) {
    int node = blockIdx.x * (blockDim.x >> 5) + (threadIdx.x >> 5);
    if (node >= NN) return;
    int lane = threadIdx.x & 31;

    float di = g_dinv[node];
    int beg = g_rowptr[node], end = g_rowptr[node + 1];

    float ax = 0.f, ay = 0.f, az = 0.f, aw = 0.f;
    for (int e = beg; e < end; e++) {
        int s = g_srcs[e];
        float w = di * g_dinv[s];
        float4 v = ((const float4*)h)[(size_t)s * 32 + lane];
        ax = fmaf(w, v.x, ax);
        ay = fmaf(w, v.y, ay);
        az = fmaf(w, v.z, az);
        aw = fmaf(w, v.w, aw);
    }
    float sw = di * di;  // self-loop weight 1/deg
    float4 hv = ((const float4*)h)[(size_t)node * 32 + lane];
    ax = fmaf(sw, hv.x, ax);
    ay = fmaf(sw, hv.y, ay);
    az = fmaf(sw, hv.z, az);
    aw = fmaf(sw, hv.w, aw);

    float4 b = ((const float4*)bias)[lane];
    float4 o;
    o.x = fmaxf(ax + b.x, 0.f);
    o.y = fmaxf(ay + b.y, 0.f);
    o.z = fmaxf(az + b.z, 0.f);
    o.w = fmaxf(aw + b.w, 0.f);
    ((float4*)out)[(size_t)node * 32 + lane] = o;
}

// ---------------- thin wrappers binding device-global buffers -------------
__global__ void k_gemm_l1(const float* __restrict__ X, const float* __restrict__ W) {
    gemm128_body(X, W, g_bufA, NN);
}
__global__ void k_agg_l1(const float* __restrict__ bias) {
    agg_body(g_bufA, bias, g_bufB);
}
__global__ void k_gemm_l2(const float* __restrict__ W) {
    gemm128_body(g_bufB, W, g_bufA, NN);
}
__global__ void k_agg_l2(const float* __restrict__ bias) {
    agg_body(g_bufA, bias, g_bufB);
}

// ---------------- head: out[n,10] = h[n,128] @ Wl[128,10] + bl -------------
__global__ void k_head(const float* __restrict__ Wl, const float* __restrict__ bl,
                       float* __restrict__ out) {
    __shared__ float Wls[C * 10];
    __shared__ float bls[10];
    const float* h = g_bufB;
    int tid = threadIdx.x;
    for (int i = tid; i < C * 10; i += blockDim.x) Wls[i] = Wl[i];
    if (tid < 10) bls[tid] = bl[tid];
    __syncthreads();

    int node = blockIdx.x * (blockDim.x >> 5) + (tid >> 5);
    if (node >= NN) return;
    int lane = tid & 31;

    float hv0 = h[(size_t)node * C + lane];
    float hv1 = h[(size_t)node * C + lane + 32];
    float hv2 = h[(size_t)node * C + lane + 64];
    float hv3 = h[(size_t)node * C + lane + 96];

    #pragma unroll
    for (int c = 0; c < 10; c++) {
        float p = hv0 * Wls[lane * 10 + c]
                + hv1 * Wls[(lane + 32) * 10 + c]
                + hv2 * Wls[(lane + 64) * 10 + c]
                + hv3 * Wls[(lane + 96) * 10 + c];
        #pragma unroll
        for (int off = 16; off > 0; off >>= 1)
            p += __shfl_down_sync(0xffffffffu, p, off);
        if (lane == 0) out[(size_t)node * 10 + c] = p + bls[c];
    }
}

// ---------------- launch (kernel launches ONLY) ----------------
extern "C" void kernel_launch(void* const* d_in, const int* in_sizes, int n_in,
                              void* d_out, int out_size) {
    const float* x   = (const float*)d_in[0];
    const int*   ei  = (const int*)d_in[1];    // int32! (JAX demotes int64)
    const float* W1  = (const float*)d_in[2];
    const float* b1  = (const float*)d_in[3];
    const float* W2  = (const float*)d_in[4];
    const float* b2  = (const float*)d_in[5];
    const float* Wl  = (const float*)d_in[6];
    const float* bl  = (const float*)d_in[7];
    float* out = (float*)d_out;

    // CSR build (recomputed every launch; deterministic inputs)
    k_zero_deg<<<(NN + 255) / 256, 256>>>();
    k_count_deg<<<(EE + 255) / 256, 256>>>(ei);
    k_dinv<<<(NN + 255) / 256, 256>>>();
    k_scan<<<1, 1024>>>();
    k_fill_csr<<<(EE + 255) / 256, 256>>>(ei);

    int gemm_grid = (NN + 31) / 32;
    int agg_grid  = (NN + 7) / 8;

    k_gemm_l1<<<gemm_grid, 256>>>(x, W1);
    k_agg_l1<<<agg_grid, 256>>>(b1);
    k_gemm_l2<<<gemm_grid, 256>>>(W2);
    k_agg_l2<<<agg_grid, 256>>>(b2);
    k_head<<<agg_grid, 256>>>(Wl, bl, out);
}

// round 4
// speedup vs baseline: 1.2930x; 1.2930x over previous
#include <cuda_runtime.h>
#include <cuda_bf16.h>
#include <stdint.h>

#define NN 50000
#define EE 800000
#define C  128
#define SCAN_BLOCKS ((NN + 1023) / 1024)   // 49

// ---------------- scratch (device globals; no allocation) ----------------
__device__ float g_bufA[(size_t)NN * C];
__device__ float g_bufB[(size_t)NN * C];
__device__ int   g_deg[NN];
__device__ float g_dinv[NN];
__device__ int   g_rowptr[NN + 1];
__device__ int   g_cnt[NN];
__device__ int   g_srcs[EE];
__device__ int   g_bsum[SCAN_BLOCKS];
__device__ int   g_boff[SCAN_BLOCKS];

// ---------------- degree / CSR ----------------
__global__ void k_zero_deg() {
    int i = blockIdx.x * blockDim.x + threadIdx.x;
    if (i < NN) g_deg[i] = 0;
}

// edge_index is int32: [2, E] row-major.
__global__ void k_count_deg(const int* __restrict__ ei) {
    int e = blockIdx.x * blockDim.x + threadIdx.x;
    if (e < EE) atomicAdd(&g_deg[ei[EE + e]], 1);
}

// Per-block exclusive scan of g_deg (shuffle-based), block sums, fused dinv.
__global__ void k_blockscan() {
    __shared__ int wsum[32];
    int tid = threadIdx.x;
    int lane = tid & 31, wid = tid >> 5;
    int i = blockIdx.x * 1024 + tid;
    int v = (i < NN) ? g_deg[i] : 0;

    if (i < NN) g_dinv[i] = rsqrtf((float)v + 1.0f);

    // inclusive warp scan
    int s = v;
    #pragma unroll
    for (int off = 1; off < 32; off <<= 1) {
        int t = __shfl_up_sync(0xffffffffu, s, off);
        if (lane >= off) s += t;
    }
    if (lane == 31) wsum[wid] = s;
    __syncthreads();
    if (wid == 0) {
        int ws = wsum[lane];
        #pragma unroll
        for (int off = 1; off < 32; off <<= 1) {
            int t = __shfl_up_sync(0xffffffffu, ws, off);
            if (lane >= off) ws += t;
        }
        wsum[lane] = ws;  // inclusive over warp sums
    }
    __syncthreads();

    int excl = s - v + (wid > 0 ? wsum[wid - 1] : 0);
    if (i < NN) g_rowptr[i] = excl;               // block-local for now
    if (tid == 1023) g_bsum[blockIdx.x] = excl + v;  // block total
}

// one warp scans the 49 block sums -> exclusive offsets; writes rowptr[NN]
__global__ void k_scansums() {
    int lane = threadIdx.x;
    int carry = 0;
    for (int base = 0; base < SCAN_BLOCKS; base += 32) {
        int idx = base + lane;
        int v = (idx < SCAN_BLOCKS) ? g_bsum[idx] : 0;
        int s = v;
        #pragma unroll
        for (int off = 1; off < 32; off <<= 1) {
            int t = __shfl_up_sync(0xffffffffu, s, off);
            if (lane >= off) s += t;
        }
        if (idx < SCAN_BLOCKS) g_boff[idx] = carry + s - v;
        carry += __shfl_sync(0xffffffffu, s, 31);
    }
    if (lane == 0) g_rowptr[NN] = carry;
}

__global__ void k_addoff() {
    int i = blockIdx.x * blockDim.x + threadIdx.x;
    if (i < NN) {
        int rp = g_rowptr[i] + g_boff[i >> 10];
        g_rowptr[i] = rp;
        g_cnt[i]    = rp;
    }
}

__global__ void k_fill_csr(const int* __restrict__ ei) {
    int e = blockIdx.x * blockDim.x + threadIdx.x;
    if (e < EE) {
        int s = ei[e];
        int d = ei[EE + e];
        int pos = atomicAdd(&g_cnt[d], 1);
        g_srcs[pos] = s;
    }
}

// ---------------- GEMM body: out[n,128] = X[n,128] @ W[128,128] ----------
__device__ __forceinline__ void gemm128_body(const float* __restrict__ X,
                                             const float* __restrict__ W,
                                             float* __restrict__ out, int n) {
    __shared__ float4 Ws4[64 * 32];  // 64 k-rows x 128 cols
    __shared__ float4 Xs4[32 * 16];  // 32 rows x 64 k-cols

    int tid = threadIdx.x;
    int warp = tid >> 5, lane = tid & 31;
    int row0 = blockIdx.x * 32;
    int r0 = warp * 4;

    float acc[4][4];
    #pragma unroll
    for (int i = 0; i < 4; i++)
        #pragma unroll
        for (int j = 0; j < 4; j++) acc[i][j] = 0.f;

    #pragma unroll
    for (int kc = 0; kc < 2; kc++) {
        const float4* W4 = (const float4*)(W + (size_t)kc * 64 * C);
        #pragma unroll
        for (int i = 0; i < 8; i++) Ws4[tid + 256 * i] = W4[tid + 256 * i];

        #pragma unroll
        for (int i = 0; i < 2; i++) {
            int idx = tid + 256 * i;
            int r = idx >> 4, k4 = idx & 15;
            float4 v = make_float4(0.f, 0.f, 0.f, 0.f);
            if (row0 + r < n)
                v = ((const float4*)X)[(size_t)(row0 + r) * 32 + kc * 16 + k4];
            Xs4[idx] = v;
        }
        __syncthreads();

        #pragma unroll 4
        for (int k4 = 0; k4 < 16; k4++) {
            float4 xv[4];
            #pragma unroll
            for (int i = 0; i < 4; i++) xv[i] = Xs4[(r0 + i) * 16 + k4];
            #pragma unroll
            for (int j = 0; j < 4; j++) {
                float4 wv = Ws4[(k4 * 4 + j) * 32 + lane];
                #pragma unroll
                for (int i = 0; i < 4; i++) {
                    float xk = (j == 0) ? xv[i].x : (j == 1) ? xv[i].y
                             : (j == 2) ? xv[i].z : xv[i].w;
                    acc[i][0] = fmaf(xk, wv.x, acc[i][0]);
                    acc[i][1] = fmaf(xk, wv.y, acc[i][1]);
                    acc[i][2] = fmaf(xk, wv.z, acc[i][2]);
                    acc[i][3] = fmaf(xk, wv.w, acc[i][3]);
                }
            }
        }
        __syncthreads();
    }

    #pragma unroll
    for (int i = 0; i < 4; i++) {
        int r = row0 + r0 + i;
        if (r < n)
            ((float4*)out)[(size_t)r * 32 + lane] =
                make_float4(acc[i][0], acc[i][1], acc[i][2], acc[i][3]);
    }
}

// ---------------- aggregation body ----------------
__device__ __forceinline__ void agg_body(const float* __restrict__ h,
                                         const float* __restrict__ bias,
                                         float* __restrict__ out) {
    int node = blockIdx.x * (blockDim.x >> 5) + (threadIdx.x >> 5);
    if (node >= NN) return;
    int lane = threadIdx.x & 31;

    float di = g_dinv[node];
    int beg = g_rowptr[node], end = g_rowptr[node + 1];

    float ax = 0.f, ay = 0.f, az = 0.f, aw = 0.f;
    for (int e = beg; e < end; e++) {
        int s = g_srcs[e];
        float w = di * g_dinv[s];
        float4 v = ((const float4*)h)[(size_t)s * 32 + lane];
        ax = fmaf(w, v.x, ax);
        ay = fmaf(w, v.y, ay);
        az = fmaf(w, v.z, az);
        aw = fmaf(w, v.w, aw);
    }
    float sw = di * di;  // self-loop weight 1/deg
    float4 hv = ((const float4*)h)[(size_t)node * 32 + lane];
    ax = fmaf(sw, hv.x, ax);
    ay = fmaf(sw, hv.y, ay);
    az = fmaf(sw, hv.z, az);
    aw = fmaf(sw, hv.w, aw);

    float4 b = ((const float4*)bias)[lane];
    float4 o;
    o.x = fmaxf(ax + b.x, 0.f);
    o.y = fmaxf(ay + b.y, 0.f);
    o.z = fmaxf(az + b.z, 0.f);
    o.w = fmaxf(aw + b.w, 0.f);
    ((float4*)out)[(size_t)node * 32 + lane] = o;
}

// ---------------- thin wrappers ----------------
__global__ void k_gemm_l1(const float* __restrict__ X, const float* __restrict__ W) {
    gemm128_body(X, W, g_bufA, NN);
}
__global__ void k_agg_l1(const float* __restrict__ bias) {
    agg_body(g_bufA, bias, g_bufB);
}
__global__ void k_gemm_l2(const float* __restrict__ W) {
    gemm128_body(g_bufB, W, g_bufA, NN);
}
__global__ void k_agg_l2(const float* __restrict__ bias) {
    agg_body(g_bufA, bias, g_bufB);
}

// ---------------- head ----------------
__global__ void k_head(const float* __restrict__ Wl, const float* __restrict__ bl,
                       float* __restrict__ out) {
    __shared__ float Wls[C * 10];
    __shared__ float bls[10];
    const float* h = g_bufB;
    int tid = threadIdx.x;
    for (int i = tid; i < C * 10; i += blockDim.x) Wls[i] = Wl[i];
    if (tid < 10) bls[tid] = bl[tid];
    __syncthreads();

    int node = blockIdx.x * (blockDim.x >> 5) + (tid >> 5);
    if (node >= NN) return;
    int lane = tid & 31;

    float hv0 = h[(size_t)node * C + lane];
    float hv1 = h[(size_t)node * C + lane + 32];
    float hv2 = h[(size_t)node * C + lane + 64];
    float hv3 = h[(size_t)node * C + lane + 96];

    #pragma unroll
    for (int c = 0; c < 10; c++) {
        float p = hv0 * Wls[lane * 10 + c]
                + hv1 * Wls[(lane + 32) * 10 + c]
                + hv2 * Wls[(lane + 64) * 10 + c]
                + hv3 * Wls[(lane + 96) * 10 + c];
        #pragma unroll
        for (int off = 16; off > 0; off >>= 1)
            p += __shfl_down_sync(0xffffffffu, p, off);
        if (lane == 0) out[(size_t)node * 10 + c] = p + bls[c];
    }
}

// ---------------- launch (kernel launches ONLY) ----------------
extern "C" void kernel_launch(void* const* d_in, const int* in_sizes, int n_in,
                              void* d_out, int out_size) {
    const float* x   = (const float*)d_in[0];
    const int*   ei  = (const int*)d_in[1];
    const float* W1  = (const float*)d_in[2];
    const float* b1  = (const float*)d_in[3];
    const float* W2  = (const float*)d_in[4];
    const float* b2  = (const float*)d_in[5];
    const float* Wl  = (const float*)d_in[6];
    const float* bl  = (const float*)d_in[7];
    float* out = (float*)d_out;

    // CSR build
    k_zero_deg<<<(NN + 255) / 256, 256>>>();
    k_count_deg<<<(EE + 255) / 256, 256>>>(ei);
    k_blockscan<<<SCAN_BLOCKS, 1024>>>();
    k_scansums<<<1, 32>>>();
    k_addoff<<<(NN + 255) / 256, 256>>>();
    k_fill_csr<<<(EE + 255) / 256, 256>>>(ei);

    int gemm_grid = (NN + 31) / 32;
    int agg_grid  = (NN + 7) / 8;

    k_gemm_l1<<<gemm_grid, 256>>>(x, W1);
    k_agg_l1<<<agg_grid, 256>>>(b1);
    k_gemm_l2<<<gemm_grid, 256>>>(W2);
    k_agg_l2<<<agg_grid, 256>>>(b2);
    k_head<<<agg_grid, 256>>>(Wl, bl, out);
}

// round 5
// speedup vs baseline: 1.6753x; 1.2956x over previous
#include <cuda_runtime.h>
#include <cuda_bf16.h>
#include <stdint.h>

#define NN 50000
#define EE 800000
#define C  128
#define SCAN_BLOCKS ((NN + 1023) / 1024)   // 49

// ---------------- scratch (device globals; no allocation) ----------------
__device__ float g_bufA[(size_t)NN * C];
__device__ float g_bufB[(size_t)NN * C];
__device__ int   g_deg[NN];
__device__ float g_dinv[NN];
__device__ int   g_rowptr[NN + 1];
__device__ int   g_cnt[NN];
__device__ int   g_srcs[EE];
__device__ int   g_bsum[SCAN_BLOCKS];

// ---------------- degree / CSR ----------------
__global__ void k_zero_deg() {
    int i = blockIdx.x * blockDim.x + threadIdx.x;
    if (i < NN) g_deg[i] = 0;
}

__global__ void k_count_deg(const int* __restrict__ ei) {
    int e = blockIdx.x * blockDim.x + threadIdx.x;
    if (e < EE) atomicAdd(&g_deg[ei[EE + e]], 1);
}

// Per-block exclusive scan of g_deg (shuffle-based), block sums, fused dinv.
__global__ void k_blockscan() {
    __shared__ int wsum[32];
    int tid = threadIdx.x;
    int lane = tid & 31, wid = tid >> 5;
    int i = blockIdx.x * 1024 + tid;
    int v = (i < NN) ? g_deg[i] : 0;

    if (i < NN) g_dinv[i] = rsqrtf((float)v + 1.0f);

    int s = v;
    #pragma unroll
    for (int off = 1; off < 32; off <<= 1) {
        int t = __shfl_up_sync(0xffffffffu, s, off);
        if (lane >= off) s += t;
    }
    if (lane == 31) wsum[wid] = s;
    __syncthreads();
    if (wid == 0) {
        int ws = wsum[lane];
        #pragma unroll
        for (int off = 1; off < 32; off <<= 1) {
            int t = __shfl_up_sync(0xffffffffu, ws, off);
            if (lane >= off) ws += t;
        }
        wsum[lane] = ws;
    }
    __syncthreads();

    int excl = s - v + (wid > 0 ? wsum[wid - 1] : 0);
    if (i < NN) g_rowptr[i] = excl;                  // block-local
    if (tid == 1023) g_bsum[blockIdx.x] = excl + v;  // block total
}

// add block offsets (scan of 49 block sums done in-smem per block)
__global__ void k_addoff() {
    __shared__ int sb[SCAN_BLOCKS + 1];
    int tid = threadIdx.x;
    if (tid < SCAN_BLOCKS) sb[tid + 1] = g_bsum[tid];
    __syncthreads();
    if (tid == 0) {
        sb[0] = 0;
        for (int j = 1; j <= SCAN_BLOCKS; j++) sb[j] += sb[j - 1];
    }
    __syncthreads();

    int i = blockIdx.x * blockDim.x + tid;
    if (i < NN) {
        int rp = g_rowptr[i] + sb[i >> 10];
        g_rowptr[i] = rp;
        g_cnt[i]    = rp;
        if (i == NN - 1) g_rowptr[NN] = rp + g_deg[i];
    }
}

__global__ void k_fill_csr(const int* __restrict__ ei) {
    int e = blockIdx.x * blockDim.x + threadIdx.x;
    if (e < EE) {
        int s = ei[e];
        int d = ei[EE + e];
        int pos = atomicAdd(&g_cnt[d], 1);
        g_srcs[pos] = s;
    }
}

// ---------------- TF32 tensor-core GEMM ----------------
// out[n,128] = X[n,128] @ W[128,128], block tile 128x128, 8 warps (2M x 4N),
// warp tile 64x32 via mma.m16n8k8.tf32, K chunked by 32.
__device__ __forceinline__ unsigned f2tf32(float f) {
    unsigned r;
    asm("cvt.rna.tf32.f32 %0, %1;" : "=r"(r) : "f"(f));
    return r;
}

__device__ __forceinline__ void mma_tf32(float* c, unsigned a0, unsigned a1,
                                         unsigned a2, unsigned a3,
                                         unsigned b0, unsigned b1) {
    asm volatile(
        "mma.sync.aligned.m16n8k8.row.col.f32.tf32.tf32.f32 "
        "{%0,%1,%2,%3}, {%4,%5,%6,%7}, {%8,%9}, {%0,%1,%2,%3};"
        : "+f"(c[0]), "+f"(c[1]), "+f"(c[2]), "+f"(c[3])
        : "r"(a0), "r"(a1), "r"(a2), "r"(a3), "r"(b0), "r"(b1));
}

#define XS_STRIDE 36
#define WS_STRIDE 136

__device__ __forceinline__ void gemm128_body(const float* __restrict__ X,
                                             const float* __restrict__ W,
                                             float* __restrict__ out, int n) {
    __shared__ unsigned Xs[128 * XS_STRIDE];  // 18.4 KB, tf32 bits
    __shared__ unsigned Ws[32 * WS_STRIDE];   // 17.4 KB

    int tid = threadIdx.x;
    int warp = tid >> 5, lane = tid & 31;
    int warp_m = warp >> 2, warp_n = warp & 3;  // 2 x 4
    int row0 = blockIdx.x * 128;
    int lq = lane & 3, lg = lane >> 2;

    float acc[4][4][4];
    #pragma unroll
    for (int mt = 0; mt < 4; mt++)
        #pragma unroll
        for (int nt = 0; nt < 4; nt++)
            #pragma unroll
            for (int k = 0; k < 4; k++) acc[mt][nt][k] = 0.f;

    #pragma unroll
    for (int kc = 0; kc < 4; kc++) {
        // X chunk: 128 rows x 32 k -> Xs
        #pragma unroll
        for (int i = 0; i < 4; i++) {
            int idx = tid + 256 * i;           // 0..1023
            int r = idx >> 3, kq = idx & 7;
            float4 v = make_float4(0.f, 0.f, 0.f, 0.f);
            if (row0 + r < n)
                v = ((const float4*)X)[(size_t)(row0 + r) * 32 + kc * 8 + kq];
            unsigned* p = &Xs[r * XS_STRIDE + kq * 4];
            p[0] = f2tf32(v.x); p[1] = f2tf32(v.y);
            p[2] = f2tf32(v.z); p[3] = f2tf32(v.w);
        }
        // W chunk: 32 k x 128 n -> Ws
        #pragma unroll
        for (int i = 0; i < 4; i++) {
            int idx = tid + 256 * i;
            int r = idx >> 5, c4 = idx & 31;
            float4 v = ((const float4*)W)[(size_t)(kc * 32 + r) * 32 + c4];
            unsigned* p = &Ws[r * WS_STRIDE + c4 * 4];
            p[0] = f2tf32(v.x); p[1] = f2tf32(v.y);
            p[2] = f2tf32(v.z); p[3] = f2tf32(v.w);
        }
        __syncthreads();

        #pragma unroll
        for (int ks = 0; ks < 4; ks++) {
            int kb = ks * 8;
            unsigned b[4][2];
            #pragma unroll
            for (int nt = 0; nt < 4; nt++) {
                int nn = warp_n * 32 + nt * 8 + lg;
                b[nt][0] = Ws[(kb + lq) * WS_STRIDE + nn];
                b[nt][1] = Ws[(kb + 4 + lq) * WS_STRIDE + nn];
            }
            #pragma unroll
            for (int mt = 0; mt < 4; mt++) {
                int mm = warp_m * 64 + mt * 16 + lg;
                unsigned a0 = Xs[mm * XS_STRIDE + kb + lq];
                unsigned a1 = Xs[(mm + 8) * XS_STRIDE + kb + lq];
                unsigned a2 = Xs[mm * XS_STRIDE + kb + 4 + lq];
                unsigned a3 = Xs[(mm + 8) * XS_STRIDE + kb + 4 + lq];
                #pragma unroll
                for (int nt = 0; nt < 4; nt++)
                    mma_tf32(acc[mt][nt], a0, a1, a2, a3, b[nt][0], b[nt][1]);
            }
        }
        __syncthreads();
    }

    // epilogue
    #pragma unroll
    for (int mt = 0; mt < 4; mt++) {
        int r = row0 + warp_m * 64 + mt * 16 + lg;
        #pragma unroll
        for (int nt = 0; nt < 4; nt++) {
            int cc = warp_n * 32 + nt * 8 + lq * 2;
            if (r < n)
                *(float2*)&out[(size_t)r * C + cc] =
                    make_float2(acc[mt][nt][0], acc[mt][nt][1]);
            if (r + 8 < n)
                *(float2*)&out[(size_t)(r + 8) * C + cc] =
                    make_float2(acc[mt][nt][2], acc[mt][nt][3]);
        }
    }
}

// ---------------- aggregation body ----------------
__device__ __forceinline__ void agg_body(const float* __restrict__ h,
                                         const float* __restrict__ bias,
                                         float* __restrict__ out) {
    int node = blockIdx.x * (blockDim.x >> 5) + (threadIdx.x >> 5);
    if (node >= NN) return;
    int lane = threadIdx.x & 31;

    float di = g_dinv[node];
    int beg = g_rowptr[node], end = g_rowptr[node + 1];

    float ax = 0.f, ay = 0.f, az = 0.f, aw = 0.f;
    for (int e = beg; e < end; e++) {
        int s = g_srcs[e];
        float w = di * g_dinv[s];
        float4 v = ((const float4*)h)[(size_t)s * 32 + lane];
        ax = fmaf(w, v.x, ax);
        ay = fmaf(w, v.y, ay);
        az = fmaf(w, v.z, az);
        aw = fmaf(w, v.w, aw);
    }
    float sw = di * di;
    float4 hv = ((const float4*)h)[(size_t)node * 32 + lane];
    ax = fmaf(sw, hv.x, ax);
    ay = fmaf(sw, hv.y, ay);
    az = fmaf(sw, hv.z, az);
    aw = fmaf(sw, hv.w, aw);

    float4 b = ((const float4*)bias)[lane];
    float4 o;
    o.x = fmaxf(ax + b.x, 0.f);
    o.y = fmaxf(ay + b.y, 0.f);
    o.z = fmaxf(az + b.z, 0.f);
    o.w = fmaxf(aw + b.w, 0.f);
    ((float4*)out)[(size_t)node * 32 + lane] = o;
}

// ---------------- thin wrappers ----------------
__global__ void k_gemm_l1(const float* __restrict__ X, const float* __restrict__ W) {
    gemm128_body(X, W, g_bufA, NN);
}
__global__ void k_agg_l1(const float* __restrict__ bias) {
    agg_body(g_bufA, bias, g_bufB);
}
__global__ void k_gemm_l2(const float* __restrict__ W) {
    gemm128_body(g_bufB, W, g_bufA, NN);
}
__global__ void k_agg_l2(const float* __restrict__ bias) {
    agg_body(g_bufA, bias, g_bufB);
}

// ---------------- head ----------------
__global__ void k_head(const float* __restrict__ Wl, const float* __restrict__ bl,
                       float* __restrict__ out) {
    __shared__ float Wls[C * 10];
    __shared__ float bls[10];
    const float* h = g_bufB;
    int tid = threadIdx.x;
    for (int i = tid; i < C * 10; i += blockDim.x) Wls[i] = Wl[i];
    if (tid < 10) bls[tid] = bl[tid];
    __syncthreads();

    int node = blockIdx.x * (blockDim.x >> 5) + (tid >> 5);
    if (node >= NN) return;
    int lane = tid & 31;

    float hv0 = h[(size_t)node * C + lane];
    float hv1 = h[(size_t)node * C + lane + 32];
    float hv2 = h[(size_t)node * C + lane + 64];
    float hv3 = h[(size_t)node * C + lane + 96];

    #pragma unroll
    for (int c = 0; c < 10; c++) {
        float p = hv0 * Wls[lane * 10 + c]
                + hv1 * Wls[(lane + 32) * 10 + c]
                + hv2 * Wls[(lane + 64) * 10 + c]
                + hv3 * Wls[(lane + 96) * 10 + c];
        #pragma unroll
        for (int off = 16; off > 0; off >>= 1)
            p += __shfl_down_sync(0xffffffffu, p, off);
        if (lane == 0) out[(size_t)node * 10 + c] = p + bls[c];
    }
}

// ---------------- launch (kernel launches ONLY) ----------------
extern "C" void kernel_launch(void* const* d_in, const int* in_sizes, int n_in,
                              void* d_out, int out_size) {
    const float* x   = (const float*)d_in[0];
    const int*   ei  = (const int*)d_in[1];
    const float* W1  = (const float*)d_in[2];
    const float* b1  = (const float*)d_in[3];
    const float* W2  = (const float*)d_in[4];
    const float* b2  = (const float*)d_in[5];
    const float* Wl  = (const float*)d_in[6];
    const float* bl  = (const float*)d_in[7];
    float* out = (float*)d_out;

    // CSR build
    k_zero_deg<<<(NN + 255) / 256, 256>>>();
    k_count_deg<<<(EE + 255) / 256, 256>>>(ei);
    k_blockscan<<<SCAN_BLOCKS, 1024>>>();
    k_addoff<<<(NN + 255) / 256, 256>>>();
    k_fill_csr<<<(EE + 255) / 256, 256>>>(ei);

    int gemm_grid = (NN + 127) / 128;  // 391
    int agg_grid  = (NN + 7) / 8;

    k_gemm_l1<<<gemm_grid, 256>>>(x, W1);
    k_agg_l1<<<agg_grid, 256>>>(b1);
    k_gemm_l2<<<gemm_grid, 256>>>(W2);
    k_agg_l2<<<agg_grid, 256>>>(b2);
    k_head<<<agg_grid, 256>>>(Wl, bl, out);
}

// round 6
// speedup vs baseline: 1.7655x; 1.0539x over previous
#include <cuda_runtime.h>
#include <cuda_bf16.h>
#include <stdint.h>

#define NN 50000
#define EE 800000
#define C  128
#define SCAN_BLOCKS ((NN + 1023) / 1024)   // 49

// ---------------- scratch (device globals; no allocation) ----------------
__device__ float g_bufA[(size_t)NN * C];   // h' (dinv-scaled gemm out)
__device__ float g_bufB[(size_t)NN * C];   // h1 (post agg/relu)
__device__ int   g_deg[NN];
__device__ float g_dinv[NN];
__device__ int   g_rowptr[NN + 1];
__device__ int   g_cnt[NN];
__device__ int   g_srcs[EE];
__device__ int   g_bsum[SCAN_BLOCKS];

// ---------------- degree / CSR ----------------
__global__ void k_zero_deg() {
    int i = blockIdx.x * blockDim.x + threadIdx.x;
    if (i < NN) g_deg[i] = 0;
}

__global__ void k_count_deg(const int* __restrict__ ei) {
    int e4 = blockIdx.x * blockDim.x + threadIdx.x;
    if (e4 < EE / 4) {
        int4 d = ((const int4*)(ei + EE))[e4];
        atomicAdd(&g_deg[d.x], 1);
        atomicAdd(&g_deg[d.y], 1);
        atomicAdd(&g_deg[d.z], 1);
        atomicAdd(&g_deg[d.w], 1);
    }
}

// Per-block exclusive scan of g_deg (shuffle-based), block sums, fused dinv.
__global__ void k_blockscan() {
    __shared__ int wsum[32];
    int tid = threadIdx.x;
    int lane = tid & 31, wid = tid >> 5;
    int i = blockIdx.x * 1024 + tid;
    int v = (i < NN) ? g_deg[i] : 0;

    if (i < NN) g_dinv[i] = rsqrtf((float)v + 1.0f);

    int s = v;
    #pragma unroll
    for (int off = 1; off < 32; off <<= 1) {
        int t = __shfl_up_sync(0xffffffffu, s, off);
        if (lane >= off) s += t;
    }
    if (lane == 31) wsum[wid] = s;
    __syncthreads();
    if (wid == 0) {
        int ws = wsum[lane];
        #pragma unroll
        for (int off = 1; off < 32; off <<= 1) {
            int t = __shfl_up_sync(0xffffffffu, ws, off);
            if (lane >= off) ws += t;
        }
        wsum[lane] = ws;
    }
    __syncthreads();

    int excl = s - v + (wid > 0 ? wsum[wid - 1] : 0);
    if (i < NN) g_rowptr[i] = excl;                  // block-local
    if (tid == 1023) g_bsum[blockIdx.x] = excl + v;  // block total
}

__global__ void k_addoff() {
    __shared__ int sb[SCAN_BLOCKS + 1];
    int tid = threadIdx.x;
    if (tid < SCAN_BLOCKS) sb[tid + 1] = g_bsum[tid];
    __syncthreads();
    if (tid == 0) {
        sb[0] = 0;
        for (int j = 1; j <= SCAN_BLOCKS; j++) sb[j] += sb[j - 1];
    }
    __syncthreads();

    int i = blockIdx.x * blockDim.x + tid;
    if (i < NN) {
        int rp = g_rowptr[i] + sb[i >> 10];
        g_rowptr[i] = rp;
        g_cnt[i]    = rp;
        if (i == NN - 1) g_rowptr[NN] = rp + g_deg[i];
    }
}

__global__ void k_fill_csr(const int* __restrict__ ei) {
    int e4 = blockIdx.x * blockDim.x + threadIdx.x;
    if (e4 < EE / 4) {
        int4 s = ((const int4*)ei)[e4];
        int4 d = ((const int4*)(ei + EE))[e4];
        g_srcs[atomicAdd(&g_cnt[d.x], 1)] = s.x;
        g_srcs[atomicAdd(&g_cnt[d.y], 1)] = s.y;
        g_srcs[atomicAdd(&g_cnt[d.z], 1)] = s.z;
        g_srcs[atomicAdd(&g_cnt[d.w], 1)] = s.w;
    }
}

// ---------------- TF32 tensor-core GEMM, epilogue scales by dinv[row] -----
__device__ __forceinline__ unsigned f2tf32(float f) {
    unsigned r;
    asm("cvt.rna.tf32.f32 %0, %1;" : "=r"(r) : "f"(f));
    return r;
}

__device__ __forceinline__ void mma_tf32(float* c, unsigned a0, unsigned a1,
                                         unsigned a2, unsigned a3,
                                         unsigned b0, unsigned b1) {
    asm volatile(
        "mma.sync.aligned.m16n8k8.row.col.f32.tf32.tf32.f32 "
        "{%0,%1,%2,%3}, {%4,%5,%6,%7}, {%8,%9}, {%0,%1,%2,%3};"
        : "+f"(c[0]), "+f"(c[1]), "+f"(c[2]), "+f"(c[3])
        : "r"(a0), "r"(a1), "r"(a2), "r"(a3), "r"(b0), "r"(b1));
}

#define XS_STRIDE 36
#define WS_STRIDE 136

__device__ __forceinline__ void gemm128_body(const float* __restrict__ X,
                                             const float* __restrict__ W,
                                             float* __restrict__ out, int n) {
    __shared__ unsigned Xs[128 * XS_STRIDE];
    __shared__ unsigned Ws[32 * WS_STRIDE];

    int tid = threadIdx.x;
    int warp = tid >> 5, lane = tid & 31;
    int warp_m = warp >> 2, warp_n = warp & 3;  // 2 x 4
    int row0 = blockIdx.x * 128;
    int lq = lane & 3, lg = lane >> 2;

    float acc[4][4][4];
    #pragma unroll
    for (int mt = 0; mt < 4; mt++)
        #pragma unroll
        for (int nt = 0; nt < 4; nt++)
            #pragma unroll
            for (int k = 0; k < 4; k++) acc[mt][nt][k] = 0.f;

    #pragma unroll
    for (int kc = 0; kc < 4; kc++) {
        #pragma unroll
        for (int i = 0; i < 4; i++) {
            int idx = tid + 256 * i;
            int r = idx >> 3, kq = idx & 7;
            float4 v = make_float4(0.f, 0.f, 0.f, 0.f);
            if (row0 + r < n)
                v = ((const float4*)X)[(size_t)(row0 + r) * 32 + kc * 8 + kq];
            unsigned* p = &Xs[r * XS_STRIDE + kq * 4];
            p[0] = f2tf32(v.x); p[1] = f2tf32(v.y);
            p[2] = f2tf32(v.z); p[3] = f2tf32(v.w);
        }
        #pragma unroll
        for (int i = 0; i < 4; i++) {
            int idx = tid + 256 * i;
            int r = idx >> 5, c4 = idx & 31;
            float4 v = ((const float4*)W)[(size_t)(kc * 32 + r) * 32 + c4];
            unsigned* p = &Ws[r * WS_STRIDE + c4 * 4];
            p[0] = f2tf32(v.x); p[1] = f2tf32(v.y);
            p[2] = f2tf32(v.z); p[3] = f2tf32(v.w);
        }
        __syncthreads();

        #pragma unroll
        for (int ks = 0; ks < 4; ks++) {
            int kb = ks * 8;
            unsigned b[4][2];
            #pragma unroll
            for (int nt = 0; nt < 4; nt++) {
                int nn = warp_n * 32 + nt * 8 + lg;
                b[nt][0] = Ws[(kb + lq) * WS_STRIDE + nn];
                b[nt][1] = Ws[(kb + 4 + lq) * WS_STRIDE + nn];
            }
            #pragma unroll
            for (int mt = 0; mt < 4; mt++) {
                int mm = warp_m * 64 + mt * 16 + lg;
                unsigned a0 = Xs[mm * XS_STRIDE + kb + lq];
                unsigned a1 = Xs[(mm + 8) * XS_STRIDE + kb + lq];
                unsigned a2 = Xs[mm * XS_STRIDE + kb + 4 + lq];
                unsigned a3 = Xs[(mm + 8) * XS_STRIDE + kb + 4 + lq];
                #pragma unroll
                for (int nt = 0; nt < 4; nt++)
                    mma_tf32(acc[mt][nt], a0, a1, a2, a3, b[nt][0], b[nt][1]);
            }
        }
        __syncthreads();
    }

    // epilogue: scale row by dinv[row] -> h'
    #pragma unroll
    for (int mt = 0; mt < 4; mt++) {
        int r = row0 + warp_m * 64 + mt * 16 + lg;
        float s0 = (r < n)     ? g_dinv[r]     : 0.f;
        float s1 = (r + 8 < n) ? g_dinv[r + 8] : 0.f;
        #pragma unroll
        for (int nt = 0; nt < 4; nt++) {
            int cc = warp_n * 32 + nt * 8 + lq * 2;
            if (r < n)
                *(float2*)&out[(size_t)r * C + cc] =
                    make_float2(acc[mt][nt][0] * s0, acc[mt][nt][1] * s0);
            if (r + 8 < n)
                *(float2*)&out[(size_t)(r + 8) * C + cc] =
                    make_float2(acc[mt][nt][2] * s1, acc[mt][nt][3] * s1);
        }
    }
}

// ---------------- aggregation over pre-normalized h' ----------------
// returns o = relu(di*(sum_{s in N} h'[s] + h'[node]) + b), per-lane float4
__device__ __forceinline__ float4 agg_row(const float4* __restrict__ hp4,
                                          const float4* __restrict__ b4,
                                          int node, int lane) {
    float di = g_dinv[node];
    int e = g_rowptr[node], end = g_rowptr[node + 1];

    float4 a0 = make_float4(0.f, 0.f, 0.f, 0.f);
    float4 a1 = make_float4(0.f, 0.f, 0.f, 0.f);
    for (; e + 1 < end; e += 2) {
        int s0 = g_srcs[e], s1 = g_srcs[e + 1];
        float4 v0 = hp4[(size_t)s0 * 32 + lane];
        float4 v1 = hp4[(size_t)s1 * 32 + lane];
        a0.x += v0.x; a0.y += v0.y; a0.z += v0.z; a0.w += v0.w;
        a1.x += v1.x; a1.y += v1.y; a1.z += v1.z; a1.w += v1.w;
    }
    if (e < end) {
        float4 v = hp4[(size_t)g_srcs[e] * 32 + lane];
        a0.x += v.x; a0.y += v.y; a0.z += v.z; a0.w += v.w;
    }
    float4 sv = hp4[(size_t)node * 32 + lane];  // self (h' already has dinv)
    a0.x += a1.x + sv.x; a0.y += a1.y + sv.y;
    a0.z += a1.z + sv.z; a0.w += a1.w + sv.w;

    float4 b = b4[lane];
    float4 o;
    o.x = fmaxf(fmaf(di, a0.x, b.x), 0.f);
    o.y = fmaxf(fmaf(di, a0.y, b.y), 0.f);
    o.z = fmaxf(fmaf(di, a0.z, b.z), 0.f);
    o.w = fmaxf(fmaf(di, a0.w, b.w), 0.f);
    return o;
}

// ---------------- layer kernels ----------------
__global__ void k_gemm_l1(const float* __restrict__ X, const float* __restrict__ W) {
    gemm128_body(X, W, g_bufA, NN);
}

__global__ void k_agg_l1(const float* __restrict__ bias) {
    int node = blockIdx.x * (blockDim.x >> 5) + (threadIdx.x >> 5);
    if (node >= NN) return;
    int lane = threadIdx.x & 31;
    float4 o = agg_row((const float4*)g_bufA, (const float4*)bias, node, lane);
    ((float4*)g_bufB)[(size_t)node * 32 + lane] = o;
}

__global__ void k_gemm_l2(const float* __restrict__ W) {
    gemm128_body(g_bufB, W, g_bufA, NN);
}

// agg layer-2 fused with the linear head: out[n,10] = h2 @ Wl + bl
__global__ void k_agg2_head(const float* __restrict__ bias,
                            const float* __restrict__ Wl,
                            const float* __restrict__ bl,
                            float* __restrict__ out) {
    __shared__ float Wls[C * 10];
    __shared__ float bls[10];
    int tid = threadIdx.x;
    for (int i = tid; i < C * 10; i += blockDim.x) Wls[i] = Wl[i];
    if (tid < 10) bls[tid] = bl[tid];
    __syncthreads();

    int node = blockIdx.x * (blockDim.x >> 5) + (tid >> 5);
    if (node >= NN) return;
    int lane = tid & 31;

    float4 o = agg_row((const float4*)g_bufA, (const float4*)bias, node, lane);

    // head: lane holds h2 elements 4*lane .. 4*lane+3
    float pc[10];
    const float* wr = &Wls[(4 * lane) * 10];
    #pragma unroll
    for (int c = 0; c < 10; c++)
        pc[c] = o.x * wr[c] + o.y * wr[10 + c] + o.z * wr[20 + c] + o.w * wr[30 + c];

    #pragma unroll
    for (int c = 0; c < 10; c++) {
        #pragma unroll
        for (int off = 16; off > 0; off >>= 1)
            pc[c] += __shfl_down_sync(0xffffffffu, pc[c], off);
    }
    if (lane == 0) {
        #pragma unroll
        for (int c = 0; c < 10; c++)
            out[(size_t)node * 10 + c] = pc[c] + bls[c];
    }
}

// ---------------- launch (kernel launches ONLY) ----------------
extern "C" void kernel_launch(void* const* d_in, const int* in_sizes, int n_in,
                              void* d_out, int out_size) {
    const float* x   = (const float*)d_in[0];
    const int*   ei  = (const int*)d_in[1];
    const float* W1  = (const float*)d_in[2];
    const float* b1  = (const float*)d_in[3];
    const float* W2  = (const float*)d_in[4];
    const float* b2  = (const float*)d_in[5];
    const float* Wl  = (const float*)d_in[6];
    const float* bl  = (const float*)d_in[7];
    float* out = (float*)d_out;

    // CSR build
    k_zero_deg<<<(NN + 255) / 256, 256>>>();
    k_count_deg<<<(EE / 4 + 255) / 256, 256>>>(ei);
    k_blockscan<<<SCAN_BLOCKS, 1024>>>();
    k_addoff<<<(NN + 255) / 256, 256>>>();
    k_fill_csr<<<(EE / 4 + 255) / 256, 256>>>(ei);

    int gemm_grid = (NN + 127) / 128;  // 391
    int agg_grid  = (NN + 7) / 8;

    k_gemm_l1<<<gemm_grid, 256>>>(x, W1);
    k_agg_l1<<<agg_grid, 256>>>(b1);
    k_gemm_l2<<<gemm_grid, 256>>>(W2);
    k_agg2_head<<<agg_grid, 256>>>(b2, Wl, bl, out);
}

// round 7
// speedup vs baseline: 2.0048x; 1.1355x over previous
#include <cuda_runtime.h>
#include <cuda_fp16.h>
#include <stdint.h>

#define NN 50000
#define EE 800000
#define C  128
#define SCAN_BLOCKS ((NN + 1023) / 1024)   // 49
#define GEMM_GRID   ((NN + 127) / 128)     // 391
#define FILL_GRID   ((EE / 4 + 255) / 256) // 782

// ---------------- scratch (device globals; no allocation) ----------------
__device__ __half g_hp[(size_t)NN * C];   // h' (dinv-scaled gemm out, fp16)
__device__ __half g_h1[(size_t)NN * C];   // h1 (post agg/relu, fp16)
__device__ int    g_deg[NN];
__device__ float  g_dinv[NN];
__device__ int    g_rowptr[NN + 1];
__device__ int    g_cnt[NN];
__device__ int    g_srcs[EE];
__device__ int    g_bsum[SCAN_BLOCKS];

// ---------------- fp16/fp32 vector helpers ----------------
__device__ __forceinline__ float4 ld4v(const float* X, size_t off4) {
    return ((const float4*)X)[off4];
}
__device__ __forceinline__ float4 ld4v(const __half* X, size_t off4) {
    uint2 u = ((const uint2*)X)[off4];
    __half2 a = *(__half2*)&u.x, b = *(__half2*)&u.y;
    float2 fa = __half22float2(a), fb = __half22float2(b);
    return make_float4(fa.x, fa.y, fb.x, fb.y);
}
__device__ __forceinline__ void st4h(__half* out, size_t off4, float4 v) {
    uint2 u;
    __half2 lo = __floats2half2_rn(v.x, v.y);
    __half2 hi = __floats2half2_rn(v.z, v.w);
    u.x = *(unsigned*)&lo; u.y = *(unsigned*)&hi;
    ((uint2*)out)[off4] = u;
}

// ---------------- degree / CSR ----------------
__global__ void k_zero_deg() {
    int i = blockIdx.x * blockDim.x + threadIdx.x;
    if (i < NN) g_deg[i] = 0;
}

__global__ void k_count_deg(const int* __restrict__ ei) {
    int e4 = blockIdx.x * blockDim.x + threadIdx.x;
    if (e4 < EE / 4) {
        int4 d = ((const int4*)(ei + EE))[e4];
        atomicAdd(&g_deg[d.x], 1);
        atomicAdd(&g_deg[d.y], 1);
        atomicAdd(&g_deg[d.z], 1);
        atomicAdd(&g_deg[d.w], 1);
    }
}

// Per-block exclusive scan of g_deg, block sums, fused dinv.
__global__ void k_blockscan() {
    __shared__ int wsum[32];
    int tid = threadIdx.x;
    int lane = tid & 31, wid = tid >> 5;
    int i = blockIdx.x * 1024 + tid;
    int v = (i < NN) ? g_deg[i] : 0;

    if (i < NN) g_dinv[i] = rsqrtf((float)v + 1.0f);

    int s = v;
    #pragma unroll
    for (int off = 1; off < 32; off <<= 1) {
        int t = __shfl_up_sync(0xffffffffu, s, off);
        if (lane >= off) s += t;
    }
    if (lane == 31) wsum[wid] = s;
    __syncthreads();
    if (wid == 0) {
        int ws = wsum[lane];
        #pragma unroll
        for (int off = 1; off < 32; off <<= 1) {
            int t = __shfl_up_sync(0xffffffffu, ws, off);
            if (lane >= off) ws += t;
        }
        wsum[lane] = ws;
    }
    __syncthreads();

    int excl = s - v + (wid > 0 ? wsum[wid - 1] : 0);
    if (i < NN) g_rowptr[i] = excl;
    if (tid == 1023) g_bsum[blockIdx.x] = excl + v;
}

__global__ void k_addoff() {
    __shared__ int sb[SCAN_BLOCKS + 1];
    int tid = threadIdx.x;
    if (tid < SCAN_BLOCKS) sb[tid + 1] = g_bsum[tid];
    __syncthreads();
    if (tid == 0) {
        sb[0] = 0;
        for (int j = 1; j <= SCAN_BLOCKS; j++) sb[j] += sb[j - 1];
    }
    __syncthreads();

    int i = blockIdx.x * blockDim.x + tid;
    if (i < NN) {
        int rp = g_rowptr[i] + sb[i >> 10];
        g_rowptr[i] = rp;
        g_cnt[i]    = rp;
        if (i == NN - 1) g_rowptr[NN] = rp + g_deg[i];
    }
}

// ---------------- TF32 tensor-core GEMM body (templated input) -----------
__device__ __forceinline__ unsigned f2tf32(float f) {
    unsigned r;
    asm("cvt.rna.tf32.f32 %0, %1;" : "=r"(r) : "f"(f));
    return r;
}

__device__ __forceinline__ void mma_tf32(float* c, unsigned a0, unsigned a1,
                                         unsigned a2, unsigned a3,
                                         unsigned b0, unsigned b1) {
    asm volatile(
        "mma.sync.aligned.m16n8k8.row.col.f32.tf32.tf32.f32 "
        "{%0,%1,%2,%3}, {%4,%5,%6,%7}, {%8,%9}, {%0,%1,%2,%3};"
        : "+f"(c[0]), "+f"(c[1]), "+f"(c[2]), "+f"(c[3])
        : "r"(a0), "r"(a1), "r"(a2), "r"(a3), "r"(b0), "r"(b1));
}

#define XS_STRIDE 36
#define WS_STRIDE 136

template <typename Tin>
__device__ __forceinline__ void gemm128_body(const Tin* __restrict__ X,
                                             const float* __restrict__ W,
                                             __half* __restrict__ out,
                                             int n, int bx) {
    __shared__ unsigned Xs[128 * XS_STRIDE];
    __shared__ unsigned Ws[32 * WS_STRIDE];

    int tid = threadIdx.x;
    int warp = tid >> 5, lane = tid & 31;
    int warp_m = warp >> 2, warp_n = warp & 3;  // 2 x 4
    int row0 = bx * 128;
    int lq = lane & 3, lg = lane >> 2;

    float acc[4][4][4];
    #pragma unroll
    for (int mt = 0; mt < 4; mt++)
        #pragma unroll
        for (int nt = 0; nt < 4; nt++)
            #pragma unroll
            for (int k = 0; k < 4; k++) acc[mt][nt][k] = 0.f;

    #pragma unroll
    for (int kc = 0; kc < 4; kc++) {
        #pragma unroll
        for (int i = 0; i < 4; i++) {
            int idx = tid + 256 * i;
            int r = idx >> 3, kq = idx & 7;
            float4 v = make_float4(0.f, 0.f, 0.f, 0.f);
            if (row0 + r < n)
                v = ld4v(X, (size_t)(row0 + r) * 32 + kc * 8 + kq);
            unsigned* p = &Xs[r * XS_STRIDE + kq * 4];
            p[0] = f2tf32(v.x); p[1] = f2tf32(v.y);
            p[2] = f2tf32(v.z); p[3] = f2tf32(v.w);
        }
        #pragma unroll
        for (int i = 0; i < 4; i++) {
            int idx = tid + 256 * i;
            int r = idx >> 5, c4 = idx & 31;
            float4 v = ((const float4*)W)[(size_t)(kc * 32 + r) * 32 + c4];
            unsigned* p = &Ws[r * WS_STRIDE + c4 * 4];
            p[0] = f2tf32(v.x); p[1] = f2tf32(v.y);
            p[2] = f2tf32(v.z); p[3] = f2tf32(v.w);
        }
        __syncthreads();

        #pragma unroll
        for (int ks = 0; ks < 4; ks++) {
            int kb = ks * 8;
            unsigned b[4][2];
            #pragma unroll
            for (int nt = 0; nt < 4; nt++) {
                int nn = warp_n * 32 + nt * 8 + lg;
                b[nt][0] = Ws[(kb + lq) * WS_STRIDE + nn];
                b[nt][1] = Ws[(kb + 4 + lq) * WS_STRIDE + nn];
            }
            #pragma unroll
            for (int mt = 0; mt < 4; mt++) {
                int mm = warp_m * 64 + mt * 16 + lg;
                unsigned a0 = Xs[mm * XS_STRIDE + kb + lq];
                unsigned a1 = Xs[(mm + 8) * XS_STRIDE + kb + lq];
                unsigned a2 = Xs[mm * XS_STRIDE + kb + 4 + lq];
                unsigned a3 = Xs[(mm + 8) * XS_STRIDE + kb + 4 + lq];
                #pragma unroll
                for (int nt = 0; nt < 4; nt++)
                    mma_tf32(acc[mt][nt], a0, a1, a2, a3, b[nt][0], b[nt][1]);
            }
        }
        __syncthreads();
    }

    // epilogue: scale row by dinv[row], write fp16
    #pragma unroll
    for (int mt = 0; mt < 4; mt++) {
        int r = row0 + warp_m * 64 + mt * 16 + lg;
        float s0 = (r < n)     ? g_dinv[r]     : 0.f;
        float s1 = (r + 8 < n) ? g_dinv[r + 8] : 0.f;
        #pragma unroll
        for (int nt = 0; nt < 4; nt++) {
            int cc = warp_n * 32 + nt * 8 + lq * 2;
            if (r < n) {
                __half2 h = __floats2half2_rn(acc[mt][nt][0] * s0, acc[mt][nt][1] * s0);
                *(__half2*)&out[(size_t)r * C + cc] = h;
            }
            if (r + 8 < n) {
                __half2 h = __floats2half2_rn(acc[mt][nt][2] * s1, acc[mt][nt][3] * s1);
                *(__half2*)&out[(size_t)(r + 8) * C + cc] = h;
            }
        }
    }
}

// ---------------- fat kernel: GEMM layer1 + fill_csr ----------------
__global__ void k_gemm1_fill(const float* __restrict__ X,
                             const float* __restrict__ W,
                             const int* __restrict__ ei) {
    if (blockIdx.x < GEMM_GRID) {
        gemm128_body(X, W, g_hp, NN, blockIdx.x);
    } else {
        int e4 = (blockIdx.x - GEMM_GRID) * blockDim.x + threadIdx.x;
        if (e4 < EE / 4) {
            int4 s = ((const int4*)ei)[e4];
            int4 d = ((const int4*)(ei + EE))[e4];
            g_srcs[atomicAdd(&g_cnt[d.x], 1)] = s.x;
            g_srcs[atomicAdd(&g_cnt[d.y], 1)] = s.y;
            g_srcs[atomicAdd(&g_cnt[d.z], 1)] = s.z;
            g_srcs[atomicAdd(&g_cnt[d.w], 1)] = s.w;
        }
    }
}

// ---------------- aggregation over pre-normalized fp16 h' -----------------
__device__ __forceinline__ float4 agg_row(const __half* __restrict__ hp,
                                          const float4* __restrict__ b4,
                                          int node, int lane) {
    float di = g_dinv[node];
    int e = g_rowptr[node], end = g_rowptr[node + 1];

    float4 a0 = make_float4(0.f, 0.f, 0.f, 0.f);
    float4 a1 = make_float4(0.f, 0.f, 0.f, 0.f);
    for (; e + 1 < end; e += 2) {
        int s0 = g_srcs[e], s1 = g_srcs[e + 1];
        float4 v0 = ld4v(hp, (size_t)s0 * 32 + lane);
        float4 v1 = ld4v(hp, (size_t)s1 * 32 + lane);
        a0.x += v0.x; a0.y += v0.y; a0.z += v0.z; a0.w += v0.w;
        a1.x += v1.x; a1.y += v1.y; a1.z += v1.z; a1.w += v1.w;
    }
    if (e < end) {
        float4 v = ld4v(hp, (size_t)g_srcs[e] * 32 + lane);
        a0.x += v.x; a0.y += v.y; a0.z += v.z; a0.w += v.w;
    }
    float4 sv = ld4v(hp, (size_t)node * 32 + lane);  // self
    a0.x += a1.x + sv.x; a0.y += a1.y + sv.y;
    a0.z += a1.z + sv.z; a0.w += a1.w + sv.w;

    float4 b = b4[lane];
    float4 o;
    o.x = fmaxf(fmaf(di, a0.x, b.x), 0.f);
    o.y = fmaxf(fmaf(di, a0.y, b.y), 0.f);
    o.z = fmaxf(fmaf(di, a0.z, b.z), 0.f);
    o.w = fmaxf(fmaf(di, a0.w, b.w), 0.f);
    return o;
}

__global__ void k_agg_l1(const float* __restrict__ bias) {
    int node = blockIdx.x * (blockDim.x >> 5) + (threadIdx.x >> 5);
    if (node >= NN) return;
    int lane = threadIdx.x & 31;
    float4 o = agg_row(g_hp, (const float4*)bias, node, lane);
    st4h(g_h1, (size_t)node * 32 + lane, o);
}

__global__ void k_gemm_l2(const float* __restrict__ W) {
    gemm128_body(g_h1, W, g_hp, NN, blockIdx.x);
}

// agg layer-2 fused with linear head: out[n,10] = h2 @ Wl + bl
__global__ void k_agg2_head(const float* __restrict__ bias,
                            const float* __restrict__ Wl,
                            const float* __restrict__ bl,
                            float* __restrict__ out) {
    __shared__ float Wls[C * 10];
    __shared__ float bls[10];
    int tid = threadIdx.x;
    for (int i = tid; i < C * 10; i += blockDim.x) Wls[i] = Wl[i];
    if (tid < 10) bls[tid] = bl[tid];
    __syncthreads();

    int node = blockIdx.x * (blockDim.x >> 5) + (tid >> 5);
    if (node >= NN) return;
    int lane = tid & 31;

    float4 o = agg_row(g_hp, (const float4*)bias, node, lane);

    float pc[10];
    const float* wr = &Wls[(4 * lane) * 10];
    #pragma unroll
    for (int c = 0; c < 10; c++)
        pc[c] = o.x * wr[c] + o.y * wr[10 + c] + o.z * wr[20 + c] + o.w * wr[30 + c];

    #pragma unroll
    for (int c = 0; c < 10; c++) {
        #pragma unroll
        for (int off = 16; off > 0; off >>= 1)
            pc[c] += __shfl_down_sync(0xffffffffu, pc[c], off);
    }
    if (lane == 0) {
        #pragma unroll
        for (int c = 0; c < 10; c++)
            out[(size_t)node * 10 + c] = pc[c] + bls[c];
    }
}

// ---------------- launch (kernel launches ONLY) ----------------
extern "C" void kernel_launch(void* const* d_in, const int* in_sizes, int n_in,
                              void* d_out, int out_size) {
    const float* x   = (const float*)d_in[0];
    const int*   ei  = (const int*)d_in[1];
    const float* W1  = (const float*)d_in[2];
    const float* b1  = (const float*)d_in[3];
    const float* W2  = (const float*)d_in[4];
    const float* b2  = (const float*)d_in[5];
    const float* Wl  = (const float*)d_in[6];
    const float* bl  = (const float*)d_in[7];
    float* out = (float*)d_out;

    k_zero_deg<<<(NN + 255) / 256, 256>>>();
    k_count_deg<<<FILL_GRID, 256>>>(ei);
    k_blockscan<<<SCAN_BLOCKS, 1024>>>();       // also computes dinv
    k_addoff<<<(NN + 255) / 256, 256>>>();      // finalizes rowptr/cnt

    // GEMM layer 1 overlapped with CSR fill in one launch
    k_gemm1_fill<<<GEMM_GRID + FILL_GRID, 256>>>(x, W1, ei);

    int agg_grid = (NN + 7) / 8;
    k_agg_l1<<<agg_grid, 256>>>(b1);
    k_gemm_l2<<<GEMM_GRID, 256>>>(W2);
    k_agg2_head<<<agg_grid, 256>>>(b2, Wl, bl, out);
}

// round 8
// speedup vs baseline: 2.0091x; 1.0022x over previous
#include <cuda_runtime.h>
#include <cuda_fp16.h>
#include <stdint.h>

#define NN 50000
#define EE 800000
#define C  128
#define SCAN_BLOCKS ((NN + 1023) / 1024)   // 49
#define GEMM_GRID   ((NN + 127) / 128)     // 391
#define FILL_GRID   ((EE / 4 + 255) / 256) // 782

// ---------------- scratch (device globals; no allocation) ----------------
__device__ __half g_hp[(size_t)NN * C];   // h' (dinv-scaled gemm out, fp16)
__device__ __half g_h1[(size_t)NN * C];   // h1 (post agg/relu, fp16)
__device__ int    g_deg[NN];
__device__ float  g_dinv[NN];
__device__ int    g_rowptr[NN + 1];
__device__ int    g_cnt[NN];
__device__ int    g_srcs[EE];
__device__ int    g_bsum[SCAN_BLOCKS];

// ---------------- vector load helpers (4 consecutive k-elements) ----------
__device__ __forceinline__ float4 ld4v(const float* X, size_t off4) {
    return ((const float4*)X)[off4];
}
__device__ __forceinline__ float4 ld4v(const __half* X, size_t off4) {
    uint2 u = ((const uint2*)X)[off4];
    __half2 a = *(__half2*)&u.x, b = *(__half2*)&u.y;
    float2 fa = __half22float2(a), fb = __half22float2(b);
    return make_float4(fa.x, fa.y, fb.x, fb.y);
}
__device__ __forceinline__ void st4h(__half* out, size_t off4, float4 v) {
    uint2 u;
    __half2 lo = __floats2half2_rn(v.x, v.y);
    __half2 hi = __floats2half2_rn(v.z, v.w);
    u.x = *(unsigned*)&lo; u.y = *(unsigned*)&hi;
    ((uint2*)out)[off4] = u;
}

// ---------------- degree / CSR ----------------
__global__ void k_zero_deg() {
    int i = blockIdx.x * blockDim.x + threadIdx.x;
    if (i < NN) g_deg[i] = 0;
}

__global__ void k_count_deg(const int* __restrict__ ei) {
    int e4 = blockIdx.x * blockDim.x + threadIdx.x;
    if (e4 < EE / 4) {
        int4 d = ((const int4*)(ei + EE))[e4];
        atomicAdd(&g_deg[d.x], 1);
        atomicAdd(&g_deg[d.y], 1);
        atomicAdd(&g_deg[d.z], 1);
        atomicAdd(&g_deg[d.w], 1);
    }
}

__global__ void k_blockscan() {
    __shared__ int wsum[32];
    int tid = threadIdx.x;
    int lane = tid & 31, wid = tid >> 5;
    int i = blockIdx.x * 1024 + tid;
    int v = (i < NN) ? g_deg[i] : 0;

    if (i < NN) g_dinv[i] = rsqrtf((float)v + 1.0f);

    int s = v;
    #pragma unroll
    for (int off = 1; off < 32; off <<= 1) {
        int t = __shfl_up_sync(0xffffffffu, s, off);
        if (lane >= off) s += t;
    }
    if (lane == 31) wsum[wid] = s;
    __syncthreads();
    if (wid == 0) {
        int ws = wsum[lane];
        #pragma unroll
        for (int off = 1; off < 32; off <<= 1) {
            int t = __shfl_up_sync(0xffffffffu, ws, off);
            if (lane >= off) ws += t;
        }
        wsum[lane] = ws;
    }
    __syncthreads();

    int excl = s - v + (wid > 0 ? wsum[wid - 1] : 0);
    if (i < NN) g_rowptr[i] = excl;
    if (tid == 1023) g_bsum[blockIdx.x] = excl + v;
}

__global__ void k_addoff() {
    __shared__ int sb[SCAN_BLOCKS + 1];
    int tid = threadIdx.x;
    if (tid < SCAN_BLOCKS) sb[tid + 1] = g_bsum[tid];
    __syncthreads();
    if (tid == 0) {
        sb[0] = 0;
        for (int j = 1; j <= SCAN_BLOCKS; j++) sb[j] += sb[j - 1];
    }
    __syncthreads();

    int i = blockIdx.x * blockDim.x + tid;
    if (i < NN) {
        int rp = g_rowptr[i] + sb[i >> 10];
        g_rowptr[i] = rp;
        g_cnt[i]    = rp;
        if (i == NN - 1) g_rowptr[NN] = rp + g_deg[i];
    }
}

// ---------------- FP16 tensor-core GEMM (m16n8k16) -----------------------
// out[n,128] = dinv[r] * (X[n,128] @ W[128,128]), fp16 out.
// 8 warps (2M x 4N), warp tile 64x32, K chunked 2x64.
__device__ __forceinline__ void mma_fp16(float* c, unsigned a0, unsigned a1,
                                         unsigned a2, unsigned a3,
                                         unsigned b0, unsigned b1) {
    asm volatile(
        "mma.sync.aligned.m16n8k16.row.col.f32.f16.f16.f32 "
        "{%0,%1,%2,%3}, {%4,%5,%6,%7}, {%8,%9}, {%0,%1,%2,%3};"
        : "+f"(c[0]), "+f"(c[1]), "+f"(c[2]), "+f"(c[3])
        : "r"(a0), "r"(a1), "r"(a2), "r"(a3), "r"(b0), "r"(b1));
}

#define KS 72   // fp16 stride: bank = (r*36 + word) % 32, conflict-free frags

template <typename Tin>
__device__ __forceinline__ void gemm128_body(const Tin* __restrict__ X,
                                             const float* __restrict__ W,
                                             __half* __restrict__ out,
                                             int n, int bx) {
    __shared__ __half Xs[128 * KS];  // rows x k-chunk(64)
    __shared__ __half Wt[128 * KS];  // n x k-chunk(64)  (transposed W)

    int tid = threadIdx.x;
    int warp = tid >> 5, lane = tid & 31;
    int warp_m = warp >> 2, warp_n = warp & 3;  // 2 x 4
    int row0 = bx * 128;
    int lq = lane & 3, lg = lane >> 2;

    float acc[4][4][4];
    #pragma unroll
    for (int mt = 0; mt < 4; mt++)
        #pragma unroll
        for (int nt = 0; nt < 4; nt++)
            #pragma unroll
            for (int k = 0; k < 4; k++) acc[mt][nt][k] = 0.f;

    #pragma unroll
    for (int kc = 0; kc < 2; kc++) {
        // X chunk: 128 rows x 64 k  (2048 float4-tasks / 256 thr = 8)
        #pragma unroll
        for (int i = 0; i < 8; i++) {
            int idx = tid + 256 * i;
            int r = idx >> 4, kq = idx & 15;
            float4 v = make_float4(0.f, 0.f, 0.f, 0.f);
            if (row0 + r < n)
                v = ld4v(X, (size_t)(row0 + r) * 32 + kc * 16 + kq);
            __half2* p = (__half2*)&Xs[r * KS + kq * 4];
            p[0] = __floats2half2_rn(v.x, v.y);
            p[1] = __floats2half2_rn(v.z, v.w);
        }
        // W chunk transposed: Wt[n][k] for k in [kc*64, kc*64+64)
        // tasks: 32 k-pairs x 32 n-quads = 1024 / 256 thr = 4
        #pragma unroll
        for (int i = 0; i < 4; i++) {
            int idx = tid + 256 * i;
            int kp = idx & 31, n4 = idx >> 5;
            int k0 = kc * 64 + kp * 2;
            float4 a = ((const float4*)W)[(size_t)k0 * 32 + n4];
            float4 b = ((const float4*)W)[(size_t)(k0 + 1) * 32 + n4];
            int nb = n4 * 4;
            *(__half2*)&Wt[(nb + 0) * KS + kp * 2] = __floats2half2_rn(a.x, b.x);
            *(__half2*)&Wt[(nb + 1) * KS + kp * 2] = __floats2half2_rn(a.y, b.y);
            *(__half2*)&Wt[(nb + 2) * KS + kp * 2] = __floats2half2_rn(a.z, b.z);
            *(__half2*)&Wt[(nb + 3) * KS + kp * 2] = __floats2half2_rn(a.w, b.w);
        }
        __syncthreads();

        #pragma unroll
        for (int ks = 0; ks < 4; ks++) {
            int kb = ks * 16;
            unsigned b[4][2];
            #pragma unroll
            for (int nt = 0; nt < 4; nt++) {
                int nn = warp_n * 32 + nt * 8 + lg;
                b[nt][0] = *(unsigned*)&Wt[nn * KS + kb + 2 * lq];
                b[nt][1] = *(unsigned*)&Wt[nn * KS + kb + 8 + 2 * lq];
            }
            #pragma unroll
            for (int mt = 0; mt < 4; mt++) {
                int mm = warp_m * 64 + mt * 16 + lg;
                unsigned a0 = *(unsigned*)&Xs[mm * KS + kb + 2 * lq];
                unsigned a1 = *(unsigned*)&Xs[(mm + 8) * KS + kb + 2 * lq];
                unsigned a2 = *(unsigned*)&Xs[mm * KS + kb + 8 + 2 * lq];
                unsigned a3 = *(unsigned*)&Xs[(mm + 8) * KS + kb + 8 + 2 * lq];
                #pragma unroll
                for (int nt = 0; nt < 4; nt++)
                    mma_fp16(acc[mt][nt], a0, a1, a2, a3, b[nt][0], b[nt][1]);
            }
        }
        __syncthreads();
    }

    // epilogue: scale row by dinv[row], write fp16
    #pragma unroll
    for (int mt = 0; mt < 4; mt++) {
        int r = row0 + warp_m * 64 + mt * 16 + lg;
        float s0 = (r < n)     ? g_dinv[r]     : 0.f;
        float s1 = (r + 8 < n) ? g_dinv[r + 8] : 0.f;
        #pragma unroll
        for (int nt = 0; nt < 4; nt++) {
            int cc = warp_n * 32 + nt * 8 + lq * 2;
            if (r < n) {
                __half2 h = __floats2half2_rn(acc[mt][nt][0] * s0, acc[mt][nt][1] * s0);
                *(__half2*)&out[(size_t)r * C + cc] = h;
            }
            if (r + 8 < n) {
                __half2 h = __floats2half2_rn(acc[mt][nt][2] * s1, acc[mt][nt][3] * s1);
                *(__half2*)&out[(size_t)(r + 8) * C + cc] = h;
            }
        }
    }
}

// ---------------- fat kernel: GEMM layer1 + fill_csr ----------------
__global__ void k_gemm1_fill(const float* __restrict__ X,
                             const float* __restrict__ W,
                             const int* __restrict__ ei) {
    if (blockIdx.x < GEMM_GRID) {
        gemm128_body(X, W, g_hp, NN, blockIdx.x);
    } else {
        int e4 = (blockIdx.x - GEMM_GRID) * blockDim.x + threadIdx.x;
        if (e4 < EE / 4) {
            int4 s = ((const int4*)ei)[e4];
            int4 d = ((const int4*)(ei + EE))[e4];
            g_srcs[atomicAdd(&g_cnt[d.x], 1)] = s.x;
            g_srcs[atomicAdd(&g_cnt[d.y], 1)] = s.y;
            g_srcs[atomicAdd(&g_cnt[d.z], 1)] = s.z;
            g_srcs[atomicAdd(&g_cnt[d.w], 1)] = s.w;
        }
    }
}

// ---------------- aggregation over pre-normalized fp16 h' -----------------
__device__ __forceinline__ float4 agg_row(const __half* __restrict__ hp,
                                          const float4* __restrict__ b4,
                                          int node, int lane) {
    float di = g_dinv[node];
    int e = g_rowptr[node], end = g_rowptr[node + 1];

    float4 a0 = make_float4(0.f, 0.f, 0.f, 0.f);
    float4 a1 = make_float4(0.f, 0.f, 0.f, 0.f);
    for (; e + 1 < end; e += 2) {
        int s0 = g_srcs[e], s1 = g_srcs[e + 1];
        float4 v0 = ld4v(hp, (size_t)s0 * 32 + lane);
        float4 v1 = ld4v(hp, (size_t)s1 * 32 + lane);
        a0.x += v0.x; a0.y += v0.y; a0.z += v0.z; a0.w += v0.w;
        a1.x += v1.x; a1.y += v1.y; a1.z += v1.z; a1.w += v1.w;
    }
    if (e < end) {
        float4 v = ld4v(hp, (size_t)g_srcs[e] * 32 + lane);
        a0.x += v.x; a0.y += v.y; a0.z += v.z; a0.w += v.w;
    }
    float4 sv = ld4v(hp, (size_t)node * 32 + lane);  // self
    a0.x += a1.x + sv.x; a0.y += a1.y + sv.y;
    a0.z += a1.z + sv.z; a0.w += a1.w + sv.w;

    float4 b = b4[lane];
    float4 o;
    o.x = fmaxf(fmaf(di, a0.x, b.x), 0.f);
    o.y = fmaxf(fmaf(di, a0.y, b.y), 0.f);
    o.z = fmaxf(fmaf(di, a0.z, b.z), 0.f);
    o.w = fmaxf(fmaf(di, a0.w, b.w), 0.f);
    return o;
}

__global__ void k_agg_l1(const float* __restrict__ bias) {
    int node = blockIdx.x * (blockDim.x >> 5) + (threadIdx.x >> 5);
    if (node >= NN) return;
    int lane = threadIdx.x & 31;
    float4 o = agg_row(g_hp, (const float4*)bias, node, lane);
    st4h(g_h1, (size_t)node * 32 + lane, o);
}

__global__ void k_gemm_l2(const float* __restrict__ W) {
    gemm128_body(g_h1, W, g_hp, NN, blockIdx.x);
}

// agg layer-2 fused with linear head: out[n,10] = h2 @ Wl + bl
__global__ void k_agg2_head(const float* __restrict__ bias,
                            const float* __restrict__ Wl,
                            const float* __restrict__ bl,
                            float* __restrict__ out) {
    __shared__ float Wls[C * 10];
    __shared__ float bls[10];
    int tid = threadIdx.x;
    for (int i = tid; i < C * 10; i += blockDim.x) Wls[i] = Wl[i];
    if (tid < 10) bls[tid] = bl[tid];
    __syncthreads();

    int node = blockIdx.x * (blockDim.x >> 5) + (tid >> 5);
    if (node >= NN) return;
    int lane = tid & 31;

    float4 o = agg_row(g_hp, (const float4*)bias, node, lane);

    float pc[10];
    const float* wr = &Wls[(4 * lane) * 10];
    #pragma unroll
    for (int c = 0; c < 10; c++)
        pc[c] = o.x * wr[c] + o.y * wr[10 + c] + o.z * wr[20 + c] + o.w * wr[30 + c];

    #pragma unroll
    for (int c = 0; c < 10; c++) {
        #pragma unroll
        for (int off = 16; off > 0; off >>= 1)
            pc[c] += __shfl_down_sync(0xffffffffu, pc[c], off);
    }
    if (lane == 0) {
        #pragma unroll
        for (int c = 0; c < 10; c++)
            out[(size_t)node * 10 + c] = pc[c] + bls[c];
    }
}

// ---------------- launch (kernel launches ONLY) ----------------
extern "C" void kernel_launch(void* const* d_in, const int* in_sizes, int n_in,
                              void* d_out, int out_size) {
    const float* x   = (const float*)d_in[0];
    const int*   ei  = (const int*)d_in[1];
    const float* W1  = (const float*)d_in[2];
    const float* b1  = (const float*)d_in[3];
    const float* W2  = (const float*)d_in[4];
    const float* b2  = (const float*)d_in[5];
    const float* Wl  = (const float*)d_in[6];
    const float* bl  = (const float*)d_in[7];
    float* out = (float*)d_out;

    k_zero_deg<<<(NN + 255) / 256, 256>>>();
    k_count_deg<<<FILL_GRID, 256>>>(ei);
    k_blockscan<<<SCAN_BLOCKS, 1024>>>();       // also computes dinv
    k_addoff<<<(NN + 255) / 256, 256>>>();      // finalizes rowptr/cnt

    // GEMM layer 1 overlapped with CSR fill in one launch
    k_gemm1_fill<<<GEMM_GRID + FILL_GRID, 256>>>(x, W1, ei);

    int agg_grid = (NN + 7) / 8;
    k_agg_l1<<<agg_grid, 256>>>(b1);
    k_gemm_l2<<<GEMM_GRID, 256>>>(W2);
    k_agg2_head<<<agg_grid, 256>>>(b2, Wl, bl, out);
}